// round 12
// baseline (speedup 1.0000x reference)
#include <cuda_runtime.h>
#include <cstdint>

#define NN 100000
#define EE 3200000
#define D_IN 512
#define D_HID 16
#define N_CLS 7

typedef unsigned long long ull;

// Scratch (device globals: allocation-free per harness rules)
__device__ __align__(16) float g_h1[NN * D_HID];     // x @ W1
__device__ __align__(16) float g_agg1[NN * D_HID];   // scatter-add of h1
__device__ __align__(16) float g_h2[NN * 8];         // relu(agg1+b1) @ W2, padded 7->8
__device__ __align__(16) float g_agg2[NN * 8];       // scatter-add of h2, padded
__device__ int g_is64;                               // edge-index dtype flag

__constant__ float cw[D_IN * D_HID];                 // W1 in constant bank (32KB)

__device__ __forceinline__ void red_add_v4(float* addr, float4 v) {
    asm volatile("{ .reg .u64 ga;\n\t"
                 "cvta.to.global.u64 ga, %0;\n\t"
                 "red.global.add.v4.f32 [ga], {%1,%2,%3,%4}; }"
                 :: "l"(addr), "f"(v.x), "f"(v.y), "f"(v.z), "f"(v.w)
                 : "memory");
}

// Packed f32x2 FMA: a += x * w elementwise on two packed floats.
__device__ __forceinline__ void fma2(ull& a, ull x, ull w) {
    asm("fma.rn.f32x2 %0, %1, %2, %0;" : "+l"(a) : "l"(x), "l"(w));
}
__device__ __forceinline__ ull splat2(float f) {
    ull r;
    asm("mov.b64 %0, {%1,%1};" : "=l"(r) : "f"(f));
    return r;
}
__device__ __forceinline__ uint32_t smem_u32(const void* p) {
    uint32_t a;
    asm("{ .reg .u64 t; cvta.to.shared.u64 t, %1; cvt.u32.u64 %0, t; }"
        : "=r"(a) : "l"(p));
    return a;
}
__device__ __forceinline__ void cpa16(uint32_t dst, const void* src) {
    asm volatile("cp.async.cg.shared.global [%0], [%1], 16;" :: "r"(dst), "l"(src));
}
__device__ __forceinline__ void cpa_commit() { asm volatile("cp.async.commit_group;"); }
template <int N>
__device__ __forceinline__ void cpa_wait() {
    asm volatile("cp.async.wait_group %0;" :: "n"(N));
}

// ---------------------------------------------------------------------------
// Launch 1: edge dtype detect.  int64 ids (<2^31) -> odd 32b words all zero.
// ---------------------------------------------------------------------------
__global__ void k_detect(const int* __restrict__ ei) {
    if (threadIdx.x == 0 && blockIdx.x == 0) {
        int s = 0;
        #pragma unroll
        for (int t = 1; t < 64; t += 2) s |= ei[t];
        g_is64 = (s == 0) ? 1 : 0;
    }
}

// Launch 2: zero agg1 (graph replay => every launch).
__global__ void k_zero1() {
    int i = blockIdx.x * blockDim.x + threadIdx.x;
    if (i < NN * 4)
        reinterpret_cast<float4*>(g_agg1)[i] = make_float4(0.f, 0.f, 0.f, 0.f);
}
// Launch 3: zero agg2.
__global__ void k_zero2() {
    int i = blockIdx.x * blockDim.x + threadIdx.x;
    if (i < NN * 2)
        reinterpret_cast<float4*>(g_agg2)[i] = make_float4(0.f, 0.f, 0.f, 0.f);
}

// ---------------------------------------------------------------------------
// Launch 4: GEMM1 (x-stationary, constant-bank weights).
// Thread = node, 16 outputs in 8 packed ull regs. x tile double-buffered in
// smem via cp.async. Weights read from __constant__ at warp-UNIFORM addresses
// -> const-port broadcast loads (off the LSU/crossbar entirely).
// ---------------------------------------------------------------------------
#define G1_T   128
#define G1_KC  32
#define G1_NCH (D_IN / G1_KC)
#define G1_XP  36
#define G1_BLOCKS ((NN + G1_T - 1) / G1_T)

__global__ __launch_bounds__(G1_T) void k_gemm1(const float* __restrict__ x) {
    __shared__ float xs[2][G1_T][G1_XP];   // 36,864 B (only x staged now)

    int tid = threadIdx.x;
    int nbase = blockIdx.x * G1_T;
    int gn = nbase + tid;

    auto stage = [&](int kc, int b) {
        #pragma unroll
        for (int r = 0; r < 8; r++) {
            int idx = r * G1_T + tid;
            int mm  = idx >> 3;
            int kk4 = (idx & 7) * 4;
            int gm  = nbase + mm;
            if (gm < NN) {
                uint32_t dst = smem_u32(&xs[b][mm][kk4]);
                cpa16(dst, x + (size_t)gm * D_IN + kc * G1_KC + kk4);
            }
        }
    };

    ull acc[8];
    #pragma unroll
    for (int j = 0; j < 8; j++) acc[j] = 0ull;

    stage(0, 0);
    cpa_commit();

    for (int kc = 0; kc < G1_NCH; kc++) {
        int b = kc & 1;
        if (kc < G1_NCH - 1) {
            stage(kc + 1, (kc + 1) & 1);
            cpa_commit();
            cpa_wait<1>();
        } else {
            cpa_wait<0>();
        }
        __syncthreads();

        const float4* xrow = reinterpret_cast<const float4*>(&xs[b][tid][0]);
        const ull* wch = reinterpret_cast<const ull*>(cw + kc * (G1_KC * 16));
        #pragma unroll
        for (int g = 0; g < 8; g++) {
            float4 xv = xrow[g];           // LDS.128, conflict-free phases
            #pragma unroll
            for (int s = 0; s < 4; s++) {
                float xf = (s == 0) ? xv.x : (s == 1) ? xv.y : (s == 2) ? xv.z : xv.w;
                ull x2 = splat2(xf);
                const ull* wrow = wch + (g * 4 + s) * 8;   // uniform const addr
                #pragma unroll
                for (int j = 0; j < 8; j++)
                    fma2(acc[j], x2, wrow[j]);             // const-port broadcast
            }
        }
        __syncthreads();
    }

    if (gn < NN) {
        ulonglong2* op = reinterpret_cast<ulonglong2*>(g_h1 + (size_t)gn * 16);
        ulonglong2 v0, v1, v2, v3;
        v0.x = acc[0]; v0.y = acc[1];
        v1.x = acc[2]; v1.y = acc[3];
        v2.x = acc[4]; v2.y = acc[5];
        v3.x = acc[6]; v3.y = acc[7];
        op[0] = v0; op[1] = v1; op[2] = v2; op[3] = v3;
    }
}

// ---------------------------------------------------------------------------
// Launch 5: Scatter1: agg1[dst] += h1[src]. 4 lanes per edge, 8 edges/warp.
// ---------------------------------------------------------------------------
__global__ __launch_bounds__(256) void k_scatter1(const void* __restrict__ ei) {
    int warpGlobal = (blockIdx.x * 256 + threadIdx.x) >> 5;
    int lane = threadIdx.x & 31;
    int e_base = warpGlobal * 8;                  // EE = 50000*8*8 exactly
    int s = 0, d = 0;
    if (lane < 8) {
        int e = e_base + lane;
        if (g_is64) {
            const long long* p = (const long long*)ei;
            s = (int)p[e];
            d = (int)p[EE + e];
        } else {
            const int* p = (const int*)ei;
            s = p[e];
            d = p[EE + e];
        }
    }
    int eloc = lane >> 2;
    int src = __shfl_sync(0xffffffffu, s, eloc);
    int dst = __shfl_sync(0xffffffffu, d, eloc);
    if ((unsigned)src >= NN || (unsigned)dst >= NN) return;
    int chunk = lane & 3;
    float4 v = reinterpret_cast<const float4*>(g_h1)[src * 4 + chunk];
    red_add_v4(g_agg1 + (size_t)dst * 16 + chunk * 4, v);
}

// ---------------------------------------------------------------------------
// Launch 6: GEMM2: g_h2 = relu(agg1 + b1) @ W2 (rows padded to 8 floats)
// ---------------------------------------------------------------------------
__global__ __launch_bounds__(256) void k_gemm2(const float* __restrict__ b1,
                                               const float* __restrict__ W2) {
    __shared__ float w2s[16 * 7];
    __shared__ float b1s[16];
    if (threadIdx.x < 112) w2s[threadIdx.x] = W2[threadIdx.x];
    if (threadIdx.x < 16)  b1s[threadIdx.x] = b1[threadIdx.x];
    __syncthreads();

    int n = blockIdx.x * blockDim.x + threadIdx.x;
    if (n >= NN) return;

    const float4* ap = reinterpret_cast<const float4*>(g_agg1 + (size_t)n * 16);
    float h[16];
    float4 t0 = ap[0], t1 = ap[1], t2 = ap[2], t3 = ap[3];
    h[0] = t0.x; h[1] = t0.y; h[2]  = t0.z; h[3]  = t0.w;
    h[4] = t1.x; h[5] = t1.y; h[6]  = t1.z; h[7]  = t1.w;
    h[8] = t2.x; h[9] = t2.y; h[10] = t2.z; h[11] = t2.w;
    h[12] = t3.x; h[13] = t3.y; h[14] = t3.z; h[15] = t3.w;
    #pragma unroll
    for (int j = 0; j < 16; j++) h[j] = fmaxf(h[j] + b1s[j], 0.f);

    float o[8];
    #pragma unroll
    for (int c = 0; c < 7; c++) {
        float s = 0.f;
        #pragma unroll
        for (int j = 0; j < 16; j++) s = fmaf(h[j], w2s[j * 7 + c], s);
        o[c] = s;
    }
    o[7] = 0.f;

    float4* op = reinterpret_cast<float4*>(g_h2 + (size_t)n * 8);
    op[0] = make_float4(o[0], o[1], o[2], o[3]);
    op[1] = make_float4(o[4], o[5], o[6], o[7]);
}

// ---------------------------------------------------------------------------
// Launch 7: Scatter2: agg2[dst] += h2[src]. 2 lanes per edge, 16 edges/warp.
// ---------------------------------------------------------------------------
__global__ __launch_bounds__(256) void k_scatter2(const void* __restrict__ ei) {
    int warpGlobal = (blockIdx.x * 256 + threadIdx.x) >> 5;
    int lane = threadIdx.x & 31;
    int e_base = warpGlobal * 16;                 // EE = 25000*8*16 exactly
    int s = 0, d = 0;
    if (lane < 16) {
        int e = e_base + lane;
        if (g_is64) {
            const long long* p = (const long long*)ei;
            s = (int)p[e];
            d = (int)p[EE + e];
        } else {
            const int* p = (const int*)ei;
            s = p[e];
            d = p[EE + e];
        }
    }
    int eloc = lane >> 1;
    int src = __shfl_sync(0xffffffffu, s, eloc);
    int dst = __shfl_sync(0xffffffffu, d, eloc);
    if ((unsigned)src >= NN || (unsigned)dst >= NN) return;
    int chunk = lane & 1;
    float4 v = reinterpret_cast<const float4*>(g_h2)[src * 2 + chunk];
    red_add_v4(g_agg2 + (size_t)dst * 8 + chunk * 4, v);
}

// ---------------------------------------------------------------------------
// Launch 8: epilogue: out[n][c] = agg2[n][c] + b2[c]
// ---------------------------------------------------------------------------
__global__ void k_final(const float* __restrict__ b2, float* __restrict__ out) {
    int i = blockIdx.x * blockDim.x + threadIdx.x;
    if (i >= NN * N_CLS) return;
    int n = i / 7;
    int c = i - n * 7;
    out[i] = g_agg2[n * 8 + c] + b2[c];
}

// ---------------------------------------------------------------------------
extern "C" void kernel_launch(void* const* d_in, const int* in_sizes, int n_in,
                              void* d_out, int out_size) {
    // Map inputs by element count (all six are distinct) — immune to ordering.
    const float* x  = nullptr;
    const void*  ei = nullptr;
    const float* W1 = nullptr;
    const float* b1 = nullptr;
    const float* W2 = nullptr;
    const float* b2 = nullptr;
    for (int i = 0; i < n_in; i++) {
        switch (in_sizes[i]) {
            case NN * D_IN:        x  = (const float*)d_in[i]; break;  // 51,200,000
            case 2 * EE:           ei = d_in[i];                break;  // 6,400,000
            case D_IN * D_HID:     W1 = (const float*)d_in[i]; break;  // 8192
            case D_HID:            b1 = (const float*)d_in[i]; break;  // 16
            case D_HID * N_CLS:    W2 = (const float*)d_in[i]; break;  // 112
            case N_CLS:            b2 = (const float*)d_in[i]; break;  // 7
            default: break;
        }
    }
    float* out = (float*)d_out;

    // W1 -> constant bank (D2D async memcpy: graph-capturable)
    cudaMemcpyToSymbolAsync(cw, W1, D_IN * D_HID * sizeof(float), 0,
                            cudaMemcpyDeviceToDevice);

    k_detect<<<1, 32>>>((const int*)ei);
    k_zero1<<<(NN * 4 + 255) / 256, 256>>>();
    k_zero2<<<(NN * 2 + 255) / 256, 256>>>();
    k_gemm1<<<G1_BLOCKS, G1_T>>>(x);              // launch slot 4 -> ncu window
    k_scatter1<<<EE / 64, 256>>>(ei);
    k_gemm2<<<(NN + 255) / 256, 256>>>(b1, W2);
    k_scatter2<<<EE / 128, 256>>>(ei);
    k_final<<<(NN * N_CLS + 255) / 256, 256>>>(b2, out);
}

// round 14
// speedup vs baseline: 1.4978x; 1.4978x over previous
#include <cuda_runtime.h>
#include <cstdint>

#define NN 100000
#define EE 3200000
#define D_IN 512
#define D_HID 16
#define N_CLS 7

typedef unsigned long long ull;

// Scratch (device globals: allocation-free per harness rules)
__device__ __align__(16) float g_h1[NN * D_HID];     // x @ W1
__device__ __align__(16) float g_agg1[NN * D_HID];   // scatter-add of h1
__device__ __align__(16) float g_h2[NN * 8];         // relu(agg1+b1) @ W2, padded 7->8
__device__ __align__(16) float g_agg2[NN * 8];       // scatter-add of h2, padded
__device__ int g_is64;                               // edge-index dtype flag

__device__ __forceinline__ void red_add_v4(float* addr, float4 v) {
    asm volatile("{ .reg .u64 ga;\n\t"
                 "cvta.to.global.u64 ga, %0;\n\t"
                 "red.global.add.v4.f32 [ga], {%1,%2,%3,%4}; }"
                 :: "l"(addr), "f"(v.x), "f"(v.y), "f"(v.z), "f"(v.w)
                 : "memory");
}

__device__ __forceinline__ uint32_t smem_u32(const void* p) {
    uint32_t a;
    asm("{ .reg .u64 t; cvta.to.shared.u64 t, %1; cvt.u32.u64 %0, t; }"
        : "=r"(a) : "l"(p));
    return a;
}
__device__ __forceinline__ void cpa16(uint32_t dst, const void* src) {
    asm volatile("cp.async.cg.shared.global [%0], [%1], 16;" :: "r"(dst), "l"(src));
}
__device__ __forceinline__ void cpa_commit() { asm volatile("cp.async.commit_group;"); }
template <int N>
__device__ __forceinline__ void cpa_wait() {
    asm volatile("cp.async.wait_group %0;" :: "n"(N));
}

__device__ __forceinline__ uint32_t cvt_tf32(float f) {
    uint32_t r;
    asm("cvt.rna.tf32.f32 %0, %1;" : "=r"(r) : "f"(f));
    return r;
}
__device__ __forceinline__ void mma_tf32(float c[4],
                                         uint32_t a0, uint32_t a1, uint32_t a2, uint32_t a3,
                                         uint32_t b0, uint32_t b1) {
    asm volatile(
        "mma.sync.aligned.m16n8k8.row.col.f32.tf32.tf32.f32 "
        "{%0,%1,%2,%3}, {%4,%5,%6,%7}, {%8,%9}, {%0,%1,%2,%3};"
        : "+f"(c[0]), "+f"(c[1]), "+f"(c[2]), "+f"(c[3])
        : "r"(a0), "r"(a1), "r"(a2), "r"(a3), "r"(b0), "r"(b1));
}

// ---------------------------------------------------------------------------
// Init: zero accumulators (every launch: graph replay) + edge dtype detect.
// ---------------------------------------------------------------------------
__global__ void k_init(const int* __restrict__ ei) {
    int i = blockIdx.x * blockDim.x + threadIdx.x;
    if (i == 0) {
        int s = 0;
        #pragma unroll
        for (int t = 1; t < 64; t += 2) s |= ei[t];
        g_is64 = (s == 0) ? 1 : 0;
    }
    float4 z = make_float4(0.f, 0.f, 0.f, 0.f);
    if (i < NN * 4) reinterpret_cast<float4*>(g_agg1)[i] = z;
    int j = i - NN * 4;
    if (j >= 0 && j < NN * 2) reinterpret_cast<float4*>(g_agg2)[j] = z;
}

// ---------------------------------------------------------------------------
// GEMM1 via tensor cores (tf32 mma.sync). Warp = 32 nodes x 16 outputs.
// x tile double-buffered in smem via cp.async; W1 chunk (32x16) too.
// W pitch = 20 floats (80B rows) so every cp.async dst is 16B-aligned.
// ---------------------------------------------------------------------------
#define G1_T   128
#define G1_KC  32
#define G1_NCH (D_IN / G1_KC)
#define G1_XP  36                 // x row pitch (bank 4g+t conflict-free)
#define G1_WP  20                 // W row pitch: 80B rows, 16B-aligned quarters
#define G1_BLOCKS ((NN + G1_T - 1) / G1_T)   // 782

__global__ __launch_bounds__(G1_T) void k_gemm1(const float* __restrict__ x,
                                                const float* __restrict__ W1) {
    __shared__ float xs[2][G1_T][G1_XP];    // 36,864 B
    __shared__ float wsc[2][G1_KC][G1_WP];  //  5,120 B

    int tid = threadIdx.x;
    int w = tid >> 5, lane = tid & 31;
    int g = lane >> 2, t = lane & 3;
    int nbase = blockIdx.x * G1_T;

    auto stage = [&](int kc, int b) {
        #pragma unroll
        for (int r = 0; r < 8; r++) {
            int idx = r * G1_T + tid;
            int mm  = idx >> 3;
            int kk4 = (idx & 7) * 4;
            int gm  = nbase + mm;
            if (gm < NN)
                cpa16(smem_u32(&xs[b][mm][kk4]),
                      x + (size_t)gm * D_IN + kc * G1_KC + kk4);
        }
        // W chunk: 32 rows x 16 cols; thread -> (row k = tid>>2, quarter q)
        int k = tid >> 2, q = tid & 3;
        cpa16(smem_u32(&wsc[b][k][q * 4]),          // 80k + 16q bytes: aligned
              W1 + (size_t)(kc * G1_KC + k) * 16 + q * 4);
    };

    float c[2][2][4];
    #pragma unroll
    for (int mt = 0; mt < 2; mt++)
        #pragma unroll
        for (int nt = 0; nt < 2; nt++)
            #pragma unroll
            for (int i = 0; i < 4; i++) c[mt][nt][i] = 0.f;

    stage(0, 0);
    cpa_commit();

    for (int kc = 0; kc < G1_NCH; kc++) {
        int b = kc & 1;
        if (kc < G1_NCH - 1) {
            stage(kc + 1, (kc + 1) & 1);
            cpa_commit();
            cpa_wait<1>();
        } else {
            cpa_wait<0>();
        }
        __syncthreads();

        #pragma unroll
        for (int ks = 0; ks < 4; ks++) {
            int k0 = ks * 8;
            // B fragments (k rows t, t+4; col g) per n8 tile
            uint32_t bf[2][2];
            #pragma unroll
            for (int nt = 0; nt < 2; nt++) {
                bf[nt][0] = cvt_tf32(wsc[b][k0 + t][nt * 8 + g]);
                bf[nt][1] = cvt_tf32(wsc[b][k0 + t + 4][nt * 8 + g]);
            }
            #pragma unroll
            for (int mt = 0; mt < 2; mt++) {
                int rr = w * 32 + mt * 16 + g;
                uint32_t a0 = cvt_tf32(xs[b][rr][k0 + t]);
                uint32_t a1 = cvt_tf32(xs[b][rr + 8][k0 + t]);
                uint32_t a2 = cvt_tf32(xs[b][rr][k0 + t + 4]);
                uint32_t a3 = cvt_tf32(xs[b][rr + 8][k0 + t + 4]);
                #pragma unroll
                for (int nt = 0; nt < 2; nt++)
                    mma_tf32(c[mt][nt], a0, a1, a2, a3, bf[nt][0], bf[nt][1]);
            }
        }
        __syncthreads();
    }

    // Epilogue: c[mt][nt] -> h1 rows. Lane owns (rows g, g+8; cols 2t, 2t+1).
    #pragma unroll
    for (int mt = 0; mt < 2; mt++) {
        int node = nbase + w * 32 + mt * 16 + g;
        #pragma unroll
        for (int nt = 0; nt < 2; nt++) {
            if (node < NN) {
                float2 v = make_float2(c[mt][nt][0], c[mt][nt][1]);
                *reinterpret_cast<float2*>(g_h1 + (size_t)node * 16 + nt * 8 + 2 * t) = v;
            }
            if (node + 8 < NN) {
                float2 v = make_float2(c[mt][nt][2], c[mt][nt][3]);
                *reinterpret_cast<float2*>(g_h1 + (size_t)(node + 8) * 16 + nt * 8 + 2 * t) = v;
            }
        }
    }
}

// ---------------------------------------------------------------------------
// Scatter1: agg1[dst] += h1[src].  4 lanes per edge, 8 edges per warp.
// ---------------------------------------------------------------------------
__global__ __launch_bounds__(256) void k_scatter1(const void* __restrict__ ei) {
    int warpGlobal = (blockIdx.x * 256 + threadIdx.x) >> 5;
    int lane = threadIdx.x & 31;
    int e_base = warpGlobal * 8;                  // EE = 50000*8*8 exactly
    int s = 0, d = 0;
    if (lane < 8) {
        int e = e_base + lane;
        if (g_is64) {
            const long long* p = (const long long*)ei;
            s = (int)p[e];
            d = (int)p[EE + e];
        } else {
            const int* p = (const int*)ei;
            s = p[e];
            d = p[EE + e];
        }
    }
    int eloc = lane >> 2;
    int src = __shfl_sync(0xffffffffu, s, eloc);
    int dst = __shfl_sync(0xffffffffu, d, eloc);
    if ((unsigned)src >= NN || (unsigned)dst >= NN) return;
    int chunk = lane & 3;
    float4 v = reinterpret_cast<const float4*>(g_h1)[src * 4 + chunk];
    red_add_v4(g_agg1 + (size_t)dst * 16 + chunk * 4, v);
}

// ---------------------------------------------------------------------------
// GEMM2: g_h2 = relu(agg1 + b1) @ W2  (row padded to 8 floats, last = 0)
// ---------------------------------------------------------------------------
__global__ __launch_bounds__(256) void k_gemm2(const float* __restrict__ b1,
                                               const float* __restrict__ W2) {
    __shared__ float w2s[16 * 7];
    __shared__ float b1s[16];
    if (threadIdx.x < 112) w2s[threadIdx.x] = W2[threadIdx.x];
    if (threadIdx.x < 16)  b1s[threadIdx.x] = b1[threadIdx.x];
    __syncthreads();

    int n = blockIdx.x * blockDim.x + threadIdx.x;
    if (n >= NN) return;

    const float4* ap = reinterpret_cast<const float4*>(g_agg1 + (size_t)n * 16);
    float h[16];
    float4 t0 = ap[0], t1 = ap[1], t2 = ap[2], t3 = ap[3];
    h[0] = t0.x; h[1] = t0.y; h[2]  = t0.z; h[3]  = t0.w;
    h[4] = t1.x; h[5] = t1.y; h[6]  = t1.z; h[7]  = t1.w;
    h[8] = t2.x; h[9] = t2.y; h[10] = t2.z; h[11] = t2.w;
    h[12] = t3.x; h[13] = t3.y; h[14] = t3.z; h[15] = t3.w;
    #pragma unroll
    for (int j = 0; j < 16; j++) h[j] = fmaxf(h[j] + b1s[j], 0.f);

    float o[8];
    #pragma unroll
    for (int c = 0; c < 7; c++) {
        float s = 0.f;
        #pragma unroll
        for (int j = 0; j < 16; j++) s = fmaf(h[j], w2s[j * 7 + c], s);
        o[c] = s;
    }
    o[7] = 0.f;

    float4* op = reinterpret_cast<float4*>(g_h2 + (size_t)n * 8);
    op[0] = make_float4(o[0], o[1], o[2], o[3]);
    op[1] = make_float4(o[4], o[5], o[6], o[7]);
}

// ---------------------------------------------------------------------------
// Scatter2: agg2[dst] += h2[src].  2 lanes per edge, 16 edges per warp.
// ---------------------------------------------------------------------------
__global__ __launch_bounds__(256) void k_scatter2(const void* __restrict__ ei) {
    int warpGlobal = (blockIdx.x * 256 + threadIdx.x) >> 5;
    int lane = threadIdx.x & 31;
    int e_base = warpGlobal * 16;                 // EE = 25000*8*16 exactly
    int s = 0, d = 0;
    if (lane < 16) {
        int e = e_base + lane;
        if (g_is64) {
            const long long* p = (const long long*)ei;
            s = (int)p[e];
            d = (int)p[EE + e];
        } else {
            const int* p = (const int*)ei;
            s = p[e];
            d = p[EE + e];
        }
    }
    int eloc = lane >> 1;
    int src = __shfl_sync(0xffffffffu, s, eloc);
    int dst = __shfl_sync(0xffffffffu, d, eloc);
    if ((unsigned)src >= NN || (unsigned)dst >= NN) return;
    int chunk = lane & 1;
    float4 v = reinterpret_cast<const float4*>(g_h2)[src * 2 + chunk];
    red_add_v4(g_agg2 + (size_t)dst * 8 + chunk * 4, v);
}

// ---------------------------------------------------------------------------
// Epilogue: out[n][c] = agg2[n][c] + b2[c]
// ---------------------------------------------------------------------------
__global__ void k_final(const float* __restrict__ b2, float* __restrict__ out) {
    int i = blockIdx.x * blockDim.x + threadIdx.x;
    if (i >= NN * N_CLS) return;
    int n = i / 7;
    int c = i - n * 7;
    out[i] = g_agg2[n * 8 + c] + b2[c];
}

// ---------------------------------------------------------------------------
extern "C" void kernel_launch(void* const* d_in, const int* in_sizes, int n_in,
                              void* d_out, int out_size) {
    // Map inputs by element count (all six are distinct) — immune to ordering.
    const float* x  = nullptr;
    const void*  ei = nullptr;
    const float* W1 = nullptr;
    const float* b1 = nullptr;
    const float* W2 = nullptr;
    const float* b2 = nullptr;
    for (int i = 0; i < n_in; i++) {
        switch (in_sizes[i]) {
            case NN * D_IN:        x  = (const float*)d_in[i]; break;  // 51,200,000
            case 2 * EE:           ei = d_in[i];                break;  // 6,400,000
            case D_IN * D_HID:     W1 = (const float*)d_in[i]; break;  // 8192
            case D_HID:            b1 = (const float*)d_in[i]; break;  // 16
            case D_HID * N_CLS:    W2 = (const float*)d_in[i]; break;  // 112
            case N_CLS:            b2 = (const float*)d_in[i]; break;  // 7
            default: break;
        }
    }
    float* out = (float*)d_out;

    k_init<<<(NN * 6 + 255) / 256, 256>>>((const int*)ei);
    k_gemm1<<<G1_BLOCKS, G1_T>>>(x, W1);
    k_scatter1<<<EE / 64, 256>>>(ei);
    k_gemm2<<<(NN + 255) / 256, 256>>>(b1, W2);
    k_scatter2<<<EE / 128, 256>>>(ei);
    k_final<<<(NN * N_CLS + 255) / 256, 256>>>(b2, out);
}

// round 15
// speedup vs baseline: 1.5000x; 1.0015x over previous
#include <cuda_runtime.h>
#include <cstdint>

#define NN 100000
#define EE 3200000
#define D_IN 512
#define D_HID 16
#define N_CLS 7

typedef unsigned long long ull;

// Scratch (device globals: allocation-free per harness rules)
__device__ __align__(16) float g_h1[NN * D_HID];     // x @ W1
__device__ __align__(16) float g_agg1[NN * D_HID];   // scatter-add of h1
__device__ __align__(16) float g_h2[NN * 8];         // relu(agg1+b1) @ W2, padded 7->8
__device__ __align__(16) float g_agg2[NN * 8];       // scatter-add of h2, padded
__device__ __align__(16) float g_w1t[D_IN * D_HID];  // W1 pre-scaled + tf32-rounded
__device__ int g_is64;                               // edge-index dtype flag

__device__ __forceinline__ void red_add_v4(float* addr, float4 v) {
    asm volatile("{ .reg .u64 ga;\n\t"
                 "cvta.to.global.u64 ga, %0;\n\t"
                 "red.global.add.v4.f32 [ga], {%1,%2,%3,%4}; }"
                 :: "l"(addr), "f"(v.x), "f"(v.y), "f"(v.z), "f"(v.w)
                 : "memory");
}

__device__ __forceinline__ uint32_t smem_u32(const void* p) {
    uint32_t a;
    asm("{ .reg .u64 t; cvta.to.shared.u64 t, %1; cvt.u32.u64 %0, t; }"
        : "=r"(a) : "l"(p));
    return a;
}
__device__ __forceinline__ void cpa16(uint32_t dst, const void* src) {
    asm volatile("cp.async.cg.shared.global [%0], [%1], 16;" :: "r"(dst), "l"(src));
}
__device__ __forceinline__ void cpa_commit() { asm volatile("cp.async.commit_group;"); }
template <int N>
__device__ __forceinline__ void cpa_wait() {
    asm volatile("cp.async.wait_group %0;" :: "n"(N));
}

__device__ __forceinline__ uint32_t cvt_tf32(float f) {
    uint32_t r;
    asm("cvt.rna.tf32.f32 %0, %1;" : "=r"(r) : "f"(f));
    return r;
}
__device__ __forceinline__ void mma_tf32(float c[4],
                                         uint32_t a0, uint32_t a1, uint32_t a2, uint32_t a3,
                                         uint32_t b0, uint32_t b1) {
    asm volatile(
        "mma.sync.aligned.m16n8k8.row.col.f32.tf32.tf32.f32 "
        "{%0,%1,%2,%3}, {%4,%5,%6,%7}, {%8,%9}, {%0,%1,%2,%3};"
        : "+f"(c[0]), "+f"(c[1]), "+f"(c[2]), "+f"(c[3])
        : "r"(a0), "r"(a1), "r"(a2), "r"(a3), "r"(b0), "r"(b1));
}

// ---------------------------------------------------------------------------
// Init: zero accumulators + dtype detect + W1 pre-scale/round (every launch).
// Pre-scale by (1+2^-11) cancels the mean truncation bias of feeding raw
// fp32 x bits to tf32 mma; rna-round once here so the hot loop has no cvts.
// ---------------------------------------------------------------------------
__global__ void k_init(const int* __restrict__ ei, const float* __restrict__ W1) {
    int i = blockIdx.x * blockDim.x + threadIdx.x;
    if (i == 0) {
        int s = 0;
        #pragma unroll
        for (int t = 1; t < 64; t += 2) s |= ei[t];
        g_is64 = (s == 0) ? 1 : 0;
    }
    if (i < D_IN * D_HID)
        g_w1t[i] = __uint_as_float(cvt_tf32(W1[i] * 1.00048828125f));  // 1+2^-11
    float4 z = make_float4(0.f, 0.f, 0.f, 0.f);
    if (i < NN * 4) reinterpret_cast<float4*>(g_agg1)[i] = z;
    int j = i - NN * 4;
    if (j >= 0 && j < NN * 2) reinterpret_cast<float4*>(g_agg2)[j] = z;
}

// ---------------------------------------------------------------------------
// GEMM1 via tensor cores (tf32 mma.sync). Warp = 32 nodes x 16 outputs.
// x tile double-buffered in smem via cp.async; W (pre-converted) too.
// NO cvt in the hot loop: x fed as raw fp32 bits (truncation, bias-compensated
// via W pre-scale); W already tf32-rounded. W pitch 20 => 16B-aligned rows.
// ---------------------------------------------------------------------------
#define G1_T   128
#define G1_KC  32
#define G1_NCH (D_IN / G1_KC)
#define G1_XP  36                 // x row pitch (bank 4g+t conflict-free)
#define G1_WP  20                 // W row pitch: 80B rows, 16B-aligned quarters
#define G1_BLOCKS ((NN + G1_T - 1) / G1_T)   // 782

__global__ __launch_bounds__(G1_T) void k_gemm1(const float* __restrict__ x) {
    __shared__ float xs[2][G1_T][G1_XP];    // 36,864 B
    __shared__ float wsc[2][G1_KC][G1_WP];  //  5,120 B

    int tid = threadIdx.x;
    int w = tid >> 5, lane = tid & 31;
    int g = lane >> 2, t = lane & 3;
    int nbase = blockIdx.x * G1_T;

    auto stage = [&](int kc, int b) {
        #pragma unroll
        for (int r = 0; r < 8; r++) {
            int idx = r * G1_T + tid;
            int mm  = idx >> 3;
            int kk4 = (idx & 7) * 4;
            int gm  = nbase + mm;
            if (gm < NN)
                cpa16(smem_u32(&xs[b][mm][kk4]),
                      x + (size_t)gm * D_IN + kc * G1_KC + kk4);
        }
        int k = tid >> 2, q = tid & 3;
        cpa16(smem_u32(&wsc[b][k][q * 4]),          // 80k + 16q bytes: aligned
              g_w1t + (size_t)(kc * G1_KC + k) * 16 + q * 4);
    };

    float c[2][2][4];
    #pragma unroll
    for (int mt = 0; mt < 2; mt++)
        #pragma unroll
        for (int nt = 0; nt < 2; nt++)
            #pragma unroll
            for (int i = 0; i < 4; i++) c[mt][nt][i] = 0.f;

    stage(0, 0);
    cpa_commit();

    for (int kc = 0; kc < G1_NCH; kc++) {
        int b = kc & 1;
        if (kc < G1_NCH - 1) {
            stage(kc + 1, (kc + 1) & 1);
            cpa_commit();
            cpa_wait<1>();
        } else {
            cpa_wait<0>();
        }
        __syncthreads();

        #pragma unroll
        for (int ks = 0; ks < 4; ks++) {
            int k0 = ks * 8;
            // B fragments: pre-converted tf32 bits, plain LDS
            uint32_t bf[2][2];
            #pragma unroll
            for (int nt = 0; nt < 2; nt++) {
                bf[nt][0] = __float_as_uint(wsc[b][k0 + t][nt * 8 + g]);
                bf[nt][1] = __float_as_uint(wsc[b][k0 + t + 4][nt * 8 + g]);
            }
            #pragma unroll
            for (int mt = 0; mt < 2; mt++) {
                int rr = w * 32 + mt * 16 + g;
                // A fragments: RAW fp32 bits (tf32 truncation, bias-compensated)
                uint32_t a0 = __float_as_uint(xs[b][rr][k0 + t]);
                uint32_t a1 = __float_as_uint(xs[b][rr + 8][k0 + t]);
                uint32_t a2 = __float_as_uint(xs[b][rr][k0 + t + 4]);
                uint32_t a3 = __float_as_uint(xs[b][rr + 8][k0 + t + 4]);
                #pragma unroll
                for (int nt = 0; nt < 2; nt++)
                    mma_tf32(c[mt][nt], a0, a1, a2, a3, bf[nt][0], bf[nt][1]);
            }
        }
        __syncthreads();
    }

    // Epilogue: lane owns (rows g, g+8; cols 2t, 2t+1) per tile.
    #pragma unroll
    for (int mt = 0; mt < 2; mt++) {
        int node = nbase + w * 32 + mt * 16 + g;
        #pragma unroll
        for (int nt = 0; nt < 2; nt++) {
            if (node < NN) {
                float2 v = make_float2(c[mt][nt][0], c[mt][nt][1]);
                *reinterpret_cast<float2*>(g_h1 + (size_t)node * 16 + nt * 8 + 2 * t) = v;
            }
            if (node + 8 < NN) {
                float2 v = make_float2(c[mt][nt][2], c[mt][nt][3]);
                *reinterpret_cast<float2*>(g_h1 + (size_t)(node + 8) * 16 + nt * 8 + 2 * t) = v;
            }
        }
    }
}

// ---------------------------------------------------------------------------
// Scatter1: agg1[dst] += h1[src].  4 lanes per edge, 8 edges per warp.
// ---------------------------------------------------------------------------
__global__ __launch_bounds__(256) void k_scatter1(const void* __restrict__ ei) {
    int warpGlobal = (blockIdx.x * 256 + threadIdx.x) >> 5;
    int lane = threadIdx.x & 31;
    int e_base = warpGlobal * 8;                  // EE = 50000*8*8 exactly
    int s = 0, d = 0;
    if (lane < 8) {
        int e = e_base + lane;
        if (g_is64) {
            const long long* p = (const long long*)ei;
            s = (int)p[e];
            d = (int)p[EE + e];
        } else {
            const int* p = (const int*)ei;
            s = p[e];
            d = p[EE + e];
        }
    }
    int eloc = lane >> 2;
    int src = __shfl_sync(0xffffffffu, s, eloc);
    int dst = __shfl_sync(0xffffffffu, d, eloc);
    if ((unsigned)src >= NN || (unsigned)dst >= NN) return;
    int chunk = lane & 3;
    float4 v = reinterpret_cast<const float4*>(g_h1)[src * 4 + chunk];
    red_add_v4(g_agg1 + (size_t)dst * 16 + chunk * 4, v);
}

// ---------------------------------------------------------------------------
// GEMM2: g_h2 = relu(agg1 + b1) @ W2  (row padded to 8 floats, last = 0)
// ---------------------------------------------------------------------------
__global__ __launch_bounds__(256) void k_gemm2(const float* __restrict__ b1,
                                               const float* __restrict__ W2) {
    __shared__ float w2s[16 * 7];
    __shared__ float b1s[16];
    if (threadIdx.x < 112) w2s[threadIdx.x] = W2[threadIdx.x];
    if (threadIdx.x < 16)  b1s[threadIdx.x] = b1[threadIdx.x];
    __syncthreads();

    int n = blockIdx.x * blockDim.x + threadIdx.x;
    if (n >= NN) return;

    const float4* ap = reinterpret_cast<const float4*>(g_agg1 + (size_t)n * 16);
    float h[16];
    float4 t0 = ap[0], t1 = ap[1], t2 = ap[2], t3 = ap[3];
    h[0] = t0.x; h[1] = t0.y; h[2]  = t0.z; h[3]  = t0.w;
    h[4] = t1.x; h[5] = t1.y; h[6]  = t1.z; h[7]  = t1.w;
    h[8] = t2.x; h[9] = t2.y; h[10] = t2.z; h[11] = t2.w;
    h[12] = t3.x; h[13] = t3.y; h[14] = t3.z; h[15] = t3.w;
    #pragma unroll
    for (int j = 0; j < 16; j++) h[j] = fmaxf(h[j] + b1s[j], 0.f);

    float o[8];
    #pragma unroll
    for (int c = 0; c < 7; c++) {
        float s = 0.f;
        #pragma unroll
        for (int j = 0; j < 16; j++) s = fmaf(h[j], w2s[j * 7 + c], s);
        o[c] = s;
    }
    o[7] = 0.f;

    float4* op = reinterpret_cast<float4*>(g_h2 + (size_t)n * 8);
    op[0] = make_float4(o[0], o[1], o[2], o[3]);
    op[1] = make_float4(o[4], o[5], o[6], o[7]);
}

// ---------------------------------------------------------------------------
// Scatter2: agg2[dst] += h2[src].  2 lanes per edge, 16 edges per warp.
// ---------------------------------------------------------------------------
__global__ __launch_bounds__(256) void k_scatter2(const void* __restrict__ ei) {
    int warpGlobal = (blockIdx.x * 256 + threadIdx.x) >> 5;
    int lane = threadIdx.x & 31;
    int e_base = warpGlobal * 16;                 // EE = 25000*8*16 exactly
    int s = 0, d = 0;
    if (lane < 16) {
        int e = e_base + lane;
        if (g_is64) {
            const long long* p = (const long long*)ei;
            s = (int)p[e];
            d = (int)p[EE + e];
        } else {
            const int* p = (const int*)ei;
            s = p[e];
            d = p[EE + e];
        }
    }
    int eloc = lane >> 1;
    int src = __shfl_sync(0xffffffffu, s, eloc);
    int dst = __shfl_sync(0xffffffffu, d, eloc);
    if ((unsigned)src >= NN || (unsigned)dst >= NN) return;
    int chunk = lane & 1;
    float4 v = reinterpret_cast<const float4*>(g_h2)[src * 2 + chunk];
    red_add_v4(g_agg2 + (size_t)dst * 8 + chunk * 4, v);
}

// ---------------------------------------------------------------------------
// Epilogue: out[n][c] = agg2[n][c] + b2[c]
// ---------------------------------------------------------------------------
__global__ void k_final(const float* __restrict__ b2, float* __restrict__ out) {
    int i = blockIdx.x * blockDim.x + threadIdx.x;
    if (i >= NN * N_CLS) return;
    int n = i / 7;
    int c = i - n * 7;
    out[i] = g_agg2[n * 8 + c] + b2[c];
}

// ---------------------------------------------------------------------------
extern "C" void kernel_launch(void* const* d_in, const int* in_sizes, int n_in,
                              void* d_out, int out_size) {
    // Map inputs by element count (all six are distinct) — immune to ordering.
    const float* x  = nullptr;
    const void*  ei = nullptr;
    const float* W1 = nullptr;
    const float* b1 = nullptr;
    const float* W2 = nullptr;
    const float* b2 = nullptr;
    for (int i = 0; i < n_in; i++) {
        switch (in_sizes[i]) {
            case NN * D_IN:        x  = (const float*)d_in[i]; break;  // 51,200,000
            case 2 * EE:           ei = d_in[i];                break;  // 6,400,000
            case D_IN * D_HID:     W1 = (const float*)d_in[i]; break;  // 8192
            case D_HID:            b1 = (const float*)d_in[i]; break;  // 16
            case D_HID * N_CLS:    W2 = (const float*)d_in[i]; break;  // 112
            case N_CLS:            b2 = (const float*)d_in[i]; break;  // 7
            default: break;
        }
    }
    float* out = (float*)d_out;

    k_init<<<(NN * 6 + 255) / 256, 256>>>((const int*)ei, W1);
    k_gemm1<<<G1_BLOCKS, G1_T>>>(x);
    k_scatter1<<<EE / 64, 256>>>(ei);
    k_gemm2<<<(NN + 255) / 256, 256>>>(b1, W2);
    k_scatter2<<<EE / 128, 256>>>(ei);
    k_final<<<(NN * N_CLS + 255) / 256, 256>>>(b2, out);
}